// round 2
// baseline (speedup 1.0000x reference)
#include <cuda_runtime.h>
#include <math.h>

#define NB 32          // batch
#define NS 4096        // seq len
#define ND 512         // feature dim
#define NCHUNK 32      // S-chunks per batch
#define ROWS_PER_CHUNK (NS / NCHUNK)   // 128
#define RPI 8          // rows per inner iteration
#define T1 128         // threads kernel 1 (each owns 4 columns)
#define BIGV 10000.0f

// Partial buffers (allocation-free scratch): ~8.4 MB total
__device__ float g_psum[NB][NCHUNK][ND];
__device__ float g_pmax[NB][NCHUNK][ND];
__device__ float g_pmin[NB][NCHUNK][ND];
__device__ float g_pacc[NB][NCHUNK][ND];
__device__ float g_pm [NB][NCHUNK];
__device__ float g_pl [NB][NCHUNK];
__device__ float g_pcnt[NB][NCHUNK];

__global__ __launch_bounds__(T1) void pool_pass1(
    const float* __restrict__ x,
    const int* __restrict__ mask,     // 4-byte mask: int32 {0,1} or float32 {0.,1.} — nonzero bits test works for both
    const float* __restrict__ w)
{
    const int chunk = blockIdx.x;
    const int b     = blockIdx.y;
    const int t     = threadIdx.x;        // 0..127
    const int lane  = t & 31;
    const int wid   = t >> 5;             // 0..3
    const int c0    = t * 4;              // column base for this thread

    __shared__ float s_part[RPI][4];

    // per-thread slice of w_attn
    const float4 w4 = *reinterpret_cast<const float4*>(w + c0);

    float4 vsum = make_float4(0.f, 0.f, 0.f, 0.f);
    float4 vmax = make_float4(-BIGV, -BIGV, -BIGV, -BIGV);
    float4 vmin = make_float4( BIGV,  BIGV,  BIGV,  BIGV);
    float4 vacc = make_float4(0.f, 0.f, 0.f, 0.f);
    float m = -1e30f, l = 0.f, cnt = 0.f;

    const int row0 = chunk * ROWS_PER_CHUNK;
    const float* xb = x + (size_t)b * NS * ND;
    const int*   mb = mask + (size_t)b * NS + row0;

    for (int it = 0; it < ROWS_PER_CHUNK; it += RPI) {
        // ---- load 8 rows (this thread's 4 columns each), compute dot partials
        float4 v[RPI];
        float  p[RPI];
        #pragma unroll
        for (int r = 0; r < RPI; r++) {
            v[r] = *reinterpret_cast<const float4*>(
                       xb + (size_t)(row0 + it + r) * ND + c0);
            p[r] = v[r].x * w4.x + v[r].y * w4.y + v[r].z * w4.z + v[r].w * w4.w;
        }
        // ---- warp-level reduce each row's partial
        #pragma unroll
        for (int r = 0; r < RPI; r++) {
            #pragma unroll
            for (int off = 16; off > 0; off >>= 1)
                p[r] += __shfl_xor_sync(0xffffffffu, p[r], off);
        }
        if (lane == 0) {
            #pragma unroll
            for (int r = 0; r < RPI; r++) s_part[r][wid] = p[r];
        }
        __syncthreads();

        // ---- assemble full scores (broadcast reads), gather mask bits
        float sc[RPI];
        bool  mk[RPI];
        float newm = m;
        #pragma unroll
        for (int r = 0; r < RPI; r++) {
            sc[r] = s_part[r][0] + s_part[r][1] + s_part[r][2] + s_part[r][3];
            mk[r] = (mb[it + r] != 0);
            if (mk[r]) newm = fmaxf(newm, sc[r]);
        }
        __syncthreads();   // protect s_part for next iteration

        // ---- online softmax rescale
        const float scale = __expf(m - newm);
        m = newm;
        l *= scale;
        vacc.x *= scale; vacc.y *= scale; vacc.z *= scale; vacc.w *= scale;

        // ---- accumulate (masked rows contribute exactly 0: exp underflow)
        #pragma unroll
        for (int r = 0; r < RPI; r++) {
            if (mk[r]) {
                const float wt = __expf(sc[r] - m);
                l   += wt;
                cnt += 1.f;
                vsum.x += v[r].x; vsum.y += v[r].y; vsum.z += v[r].z; vsum.w += v[r].w;
                vmax.x = fmaxf(vmax.x, v[r].x); vmax.y = fmaxf(vmax.y, v[r].y);
                vmax.z = fmaxf(vmax.z, v[r].z); vmax.w = fmaxf(vmax.w, v[r].w);
                vmin.x = fminf(vmin.x, v[r].x); vmin.y = fminf(vmin.y, v[r].y);
                vmin.z = fminf(vmin.z, v[r].z); vmin.w = fminf(vmin.w, v[r].w);
                vacc.x += wt * v[r].x; vacc.y += wt * v[r].y;
                vacc.z += wt * v[r].z; vacc.w += wt * v[r].w;
            }
        }
    }

    // ---- write partials
    *reinterpret_cast<float4*>(&g_psum[b][chunk][c0]) = vsum;
    *reinterpret_cast<float4*>(&g_pmax[b][chunk][c0]) = vmax;
    *reinterpret_cast<float4*>(&g_pmin[b][chunk][c0]) = vmin;
    *reinterpret_cast<float4*>(&g_pacc[b][chunk][c0]) = vacc;
    if (t == 0) {
        g_pm[b][chunk]   = m;
        g_pl[b][chunk]   = l;
        g_pcnt[b][chunk] = cnt;
    }
}

__global__ __launch_bounds__(ND) void pool_pass2(float* __restrict__ out)
{
    const int b = blockIdx.x;
    const int d = threadIdx.x;   // 0..511

    // global max for the softmax combine (broadcast loads, cheap)
    float M = -1e30f;
    #pragma unroll 4
    for (int c = 0; c < NCHUNK; c++) M = fmaxf(M, g_pm[b][c]);

    float sum = 0.f, mx = -BIGV, mn = BIGV, acc = 0.f, l = 0.f, cnt = 0.f;
    #pragma unroll 4
    for (int c = 0; c < NCHUNK; c++) {
        const float sc = __expf(g_pm[b][c] - M);
        sum += g_psum[b][c][d];
        mx   = fmaxf(mx, g_pmax[b][c][d]);
        mn   = fminf(mn, g_pmin[b][c][d]);
        acc += g_pacc[b][c][d] * sc;
        l   += g_pl[b][c] * sc;
        cnt += g_pcnt[b][c];
    }

    float* ob = out + (size_t)b * (4 * ND);
    ob[d]            = sum / (cnt + 1e-6f);
    ob[ND + d]       = mx;
    ob[2 * ND + d]   = mn;
    ob[3 * ND + d]   = acc / l;
}

extern "C" void kernel_launch(void* const* d_in, const int* in_sizes, int n_in,
                              void* d_out, int out_size)
{
    const float* x   = (const float*)d_in[0];
    const int*   mk  = (const int*)d_in[1];
    const float* w   = (const float*)d_in[2];
    float* out       = (float*)d_out;

    dim3 grid1(NCHUNK, NB);
    pool_pass1<<<grid1, T1>>>(x, mk, w);
    pool_pass2<<<NB, ND>>>(out);
}

// round 3
// speedup vs baseline: 1.1805x; 1.1805x over previous
#include <cuda_runtime.h>
#include <math.h>

#define NB 32
#define NS 4096
#define ND 512
#define NCHUNK 32
#define ROWS_PER_CHUNK (NS / NCHUNK)   // 128
#define RPI 8
#define T1 128
#define BIGV 10000.0f

__device__ float g_psum[NB][NCHUNK][ND];
__device__ float g_pmax[NB][NCHUNK][ND];
__device__ float g_pmin[NB][NCHUNK][ND];
__device__ float g_pacc[NB][NCHUNK][ND];
__device__ float g_pm [NB][NCHUNK];
__device__ float g_pl [NB][NCHUNK];
__device__ float g_pcnt[NB][NCHUNK];

__global__ __launch_bounds__(T1) void pool_pass1(
    const float* __restrict__ x,
    const int* __restrict__ mask,    // 4-byte mask: int32 {0,1} or f32 {0.,1.} — nonzero-bits test exact for both
    const float* __restrict__ w)
{
    const int chunk = blockIdx.x;
    const int b     = blockIdx.y;
    const int t     = threadIdx.x;
    const int lane  = t & 31;
    const int wid   = t >> 5;
    const int c0    = t * 4;

    __shared__ float s_part[2][RPI][4];

    const float4 w4 = *reinterpret_cast<const float4*>(w + c0);

    float4 vsum = make_float4(0.f, 0.f, 0.f, 0.f);
    float4 vmax = make_float4(-BIGV, -BIGV, -BIGV, -BIGV);
    float4 vmin = make_float4( BIGV,  BIGV,  BIGV,  BIGV);
    float4 vacc = make_float4(0.f, 0.f, 0.f, 0.f);
    float m = -1e30f, l = 0.f, cnt = 0.f;

    const int row0 = chunk * ROWS_PER_CHUNK;
    const float* xb = x + (size_t)b * NS * ND;
    const int*   mb = mask + (size_t)b * NS + row0;

    int buf = 0;
    for (int it = 0; it < ROWS_PER_CHUNK; it += RPI, buf ^= 1) {
        // ---- mask first: skip loads of masked rows entirely (mk uniform per block)
        bool mk[RPI];
        #pragma unroll
        for (int r = 0; r < RPI; r++) mk[r] = (mb[it + r] != 0);

        float4 v[RPI];
        float  p[RPI];
        #pragma unroll
        for (int r = 0; r < RPI; r++) {
            if (mk[r]) {
                v[r] = *reinterpret_cast<const float4*>(
                           xb + (size_t)(row0 + it + r) * ND + c0);
                p[r] = v[r].x * w4.x + v[r].y * w4.y + v[r].z * w4.z + v[r].w * w4.w;
            }
        }
        #pragma unroll
        for (int r = 0; r < RPI; r++) {
            if (mk[r]) {
                #pragma unroll
                for (int off = 16; off > 0; off >>= 1)
                    p[r] += __shfl_xor_sync(0xffffffffu, p[r], off);
            }
        }
        if (lane == 0) {
            #pragma unroll
            for (int r = 0; r < RPI; r++)
                s_part[buf][r][wid] = mk[r] ? p[r] : 0.f;
        }
        __syncthreads();   // single barrier; double-buffer protects reuse

        float sc[RPI];
        float newm = m;
        #pragma unroll
        for (int r = 0; r < RPI; r++) {
            if (mk[r]) {
                sc[r] = s_part[buf][r][0] + s_part[buf][r][1]
                      + s_part[buf][r][2] + s_part[buf][r][3];
                newm = fmaxf(newm, sc[r]);
            }
        }

        const float scale = __expf(m - newm);
        m = newm;
        l *= scale;
        vacc.x *= scale; vacc.y *= scale; vacc.z *= scale; vacc.w *= scale;

        #pragma unroll
        for (int r = 0; r < RPI; r++) {
            if (mk[r]) {
                const float wt = __expf(sc[r] - m);
                l   += wt;
                cnt += 1.f;
                vsum.x += v[r].x; vsum.y += v[r].y; vsum.z += v[r].z; vsum.w += v[r].w;
                vmax.x = fmaxf(vmax.x, v[r].x); vmax.y = fmaxf(vmax.y, v[r].y);
                vmax.z = fmaxf(vmax.z, v[r].z); vmax.w = fmaxf(vmax.w, v[r].w);
                vmin.x = fminf(vmin.x, v[r].x); vmin.y = fminf(vmin.y, v[r].y);
                vmin.z = fminf(vmin.z, v[r].z); vmin.w = fminf(vmin.w, v[r].w);
                vacc.x += wt * v[r].x; vacc.y += wt * v[r].y;
                vacc.z += wt * v[r].z; vacc.w += wt * v[r].w;
            }
        }
    }

    *reinterpret_cast<float4*>(&g_psum[b][chunk][c0]) = vsum;
    *reinterpret_cast<float4*>(&g_pmax[b][chunk][c0]) = vmax;
    *reinterpret_cast<float4*>(&g_pmin[b][chunk][c0]) = vmin;
    *reinterpret_cast<float4*>(&g_pacc[b][chunk][c0]) = vacc;
    if (t == 0) {
        g_pm[b][chunk]   = m;
        g_pl[b][chunk]   = l;
        g_pcnt[b][chunk] = cnt;
    }
}

// grid (NB, 8): each block = 64 columns of one batch; 8 slices of 4 chunks over threads.
#define T2 512
#define COLS_PER_BLK 64
#define NSLICE 8
#define CHUNKS_PER_SLICE (NCHUNK / NSLICE)  // 4

__global__ __launch_bounds__(T2) void pool_pass2(float* __restrict__ out)
{
    const int b     = blockIdx.x;
    const int tid   = threadIdx.x;
    const int col   = blockIdx.y * COLS_PER_BLK + (tid & (COLS_PER_BLK - 1));
    const int slice = tid >> 6;   // 0..7

    __shared__ float s_sum[NSLICE][COLS_PER_BLK];
    __shared__ float s_max[NSLICE][COLS_PER_BLK];
    __shared__ float s_min[NSLICE][COLS_PER_BLK];
    __shared__ float s_acc[NSLICE][COLS_PER_BLK];

    // global softmax max M + scalar l/cnt (broadcast loads, redundant per thread)
    float M = -1e30f;
    #pragma unroll
    for (int c = 0; c < NCHUNK; c++) M = fmaxf(M, g_pm[b][c]);
    float l = 0.f, cnt = 0.f;
    #pragma unroll
    for (int c = 0; c < NCHUNK; c++) {
        l   += g_pl[b][c] * __expf(g_pm[b][c] - M);
        cnt += g_pcnt[b][c];
    }

    float sum = 0.f, mx = -BIGV, mn = BIGV, acc = 0.f;
    const int cbase = slice * CHUNKS_PER_SLICE;
    #pragma unroll
    for (int i = 0; i < CHUNKS_PER_SLICE; i++) {
        const int c = cbase + i;
        sum += g_psum[b][c][col];
        mx   = fmaxf(mx, g_pmax[b][c][col]);
        mn   = fminf(mn, g_pmin[b][c][col]);
        acc += g_pacc[b][c][col] * __expf(g_pm[b][c] - M);
    }

    const int lc = tid & (COLS_PER_BLK - 1);
    s_sum[slice][lc] = sum;
    s_max[slice][lc] = mx;
    s_min[slice][lc] = mn;
    s_acc[slice][lc] = acc;
    __syncthreads();

    if (slice == 0) {
        #pragma unroll
        for (int s = 1; s < NSLICE; s++) {
            sum += s_sum[s][lc];
            mx   = fmaxf(mx, s_max[s][lc]);
            mn   = fminf(mn, s_min[s][lc]);
            acc += s_acc[s][lc];
        }
        float* ob = out + (size_t)b * (4 * ND);
        ob[col]          = sum / (cnt + 1e-6f);
        ob[ND + col]     = mx;
        ob[2 * ND + col] = mn;
        ob[3 * ND + col] = acc / l;
    }
}

extern "C" void kernel_launch(void* const* d_in, const int* in_sizes, int n_in,
                              void* d_out, int out_size)
{
    const float* x  = (const float*)d_in[0];
    const int*   mk = (const int*)d_in[1];
    const float* w  = (const float*)d_in[2];
    float* out      = (float*)d_out;

    dim3 grid1(NCHUNK, NB);
    pool_pass1<<<grid1, T1>>>(x, mk, w);
    dim3 grid2(NB, ND / COLS_PER_BLK);   // (32, 8)
    pool_pass2<<<grid2, T2>>>(out);
}

// round 4
// speedup vs baseline: 1.8450x; 1.5628x over previous
#include <cuda_runtime.h>
#include <math.h>

#define NB 32
#define NS 4096
#define ND 512
#define NCHUNK 32
#define ROWS_PER_CHUNK (NS / NCHUNK)   // 128
#define T1 128
#define BIGV 10000.0f

__device__ float g_psum[NB][NCHUNK][ND];
__device__ float g_pmax[NB][NCHUNK][ND];
__device__ float g_pmin[NB][NCHUNK][ND];
__device__ float g_pacc[NB][NCHUNK][ND];
__device__ float g_pm [NB][NCHUNK];
__device__ float g_pl [NB][NCHUNK];
__device__ float g_pcnt[NB][NCHUNK];

__device__ __forceinline__ float dot4(const float4& a, const float4& b) {
    return a.x * b.x + a.y * b.y + a.z * b.z + a.w * b.w;
}

__global__ __launch_bounds__(T1) void pool_pass1(
    const float* __restrict__ x,
    const int* __restrict__ mask,   // 4-byte mask (int32 {0,1} or f32 {0.,1.}): nonzero-bits test exact for both
    const float* __restrict__ w)
{
    const int chunk = blockIdx.x;
    const int b     = blockIdx.y;
    const int t     = threadIdx.x;
    const int lane  = t & 31;
    const int wid   = t >> 5;          // 4 warps; warp owns 32 contiguous rows

    __shared__ int   s_list[4][32];
    __shared__ float s_m[4], s_l[4], s_cnt[4];
    __shared__ float s_mrg[4][4][ND];  // [type][warp][col] = 32 KB

    // thread's 16 columns: lane*4 + k*128
    float4 w4[4];
    #pragma unroll
    for (int k = 0; k < 4; k++)
        w4[k] = *reinterpret_cast<const float4*>(w + k * 128 + lane * 4);

    float4 vsum[4], vmax[4], vmin[4], vacc[4];
    #pragma unroll
    for (int k = 0; k < 4; k++) {
        vsum[k] = make_float4(0.f, 0.f, 0.f, 0.f);
        vmax[k] = make_float4(-BIGV, -BIGV, -BIGV, -BIGV);
        vmin[k] = make_float4( BIGV,  BIGV,  BIGV,  BIGV);
        vacc[k] = make_float4(0.f, 0.f, 0.f, 0.f);
    }
    float m = -1e30f, l = 0.f, cnt = 0.f;

    const int rowbase = chunk * ROWS_PER_CHUNK + wid * 32;
    const float* xb = x + (size_t)b * NS * ND;

    // ---- compact active rows (coalesced mask load + ballot)
    const bool a = (mask[(size_t)b * NS + rowbase + lane] != 0);
    const unsigned bal = __ballot_sync(0xffffffffu, a);
    const int pos = __popc(bal & ((1u << lane) - 1u));
    if (a) s_list[wid][pos] = lane;
    const int nact = __popc(bal);
    __syncwarp();

    // ---- dense main loop over active rows only: unconditional loads, warp-local reduce
    int i = 0;
    for (; i + 2 <= nact; i += 2) {
        const int r0 = s_list[wid][i];
        const int r1 = s_list[wid][i + 1];
        const float* p0 = xb + (size_t)(rowbase + r0) * ND + lane * 4;
        const float* p1 = xb + (size_t)(rowbase + r1) * ND + lane * 4;
        float4 v0[4], v1[4];
        #pragma unroll
        for (int k = 0; k < 4; k++) v0[k] = *reinterpret_cast<const float4*>(p0 + k * 128);
        #pragma unroll
        for (int k = 0; k < 4; k++) v1[k] = *reinterpret_cast<const float4*>(p1 + k * 128);

        float d0 = dot4(v0[0], w4[0]) + dot4(v0[1], w4[1]) + dot4(v0[2], w4[2]) + dot4(v0[3], w4[3]);
        float d1 = dot4(v1[0], w4[0]) + dot4(v1[1], w4[1]) + dot4(v1[2], w4[2]) + dot4(v1[3], w4[3]);
        #pragma unroll
        for (int off = 16; off > 0; off >>= 1) {
            d0 += __shfl_xor_sync(0xffffffffu, d0, off);
            d1 += __shfl_xor_sync(0xffffffffu, d1, off);
        }

        const float newm  = fmaxf(m, fmaxf(d0, d1));
        const float scale = __expf(m - newm);
        m = newm;
        l *= scale;
        const float e0 = __expf(d0 - m);
        const float e1 = __expf(d1 - m);
        l += e0 + e1;
        cnt += 2.f;
        #pragma unroll
        for (int k = 0; k < 4; k++) {
            vacc[k].x = vacc[k].x * scale + e0 * v0[k].x + e1 * v1[k].x;
            vacc[k].y = vacc[k].y * scale + e0 * v0[k].y + e1 * v1[k].y;
            vacc[k].z = vacc[k].z * scale + e0 * v0[k].z + e1 * v1[k].z;
            vacc[k].w = vacc[k].w * scale + e0 * v0[k].w + e1 * v1[k].w;
            vsum[k].x += v0[k].x + v1[k].x; vsum[k].y += v0[k].y + v1[k].y;
            vsum[k].z += v0[k].z + v1[k].z; vsum[k].w += v0[k].w + v1[k].w;
            vmax[k].x = fmaxf(vmax[k].x, fmaxf(v0[k].x, v1[k].x));
            vmax[k].y = fmaxf(vmax[k].y, fmaxf(v0[k].y, v1[k].y));
            vmax[k].z = fmaxf(vmax[k].z, fmaxf(v0[k].z, v1[k].z));
            vmax[k].w = fmaxf(vmax[k].w, fmaxf(v0[k].w, v1[k].w));
            vmin[k].x = fminf(vmin[k].x, fminf(v0[k].x, v1[k].x));
            vmin[k].y = fminf(vmin[k].y, fminf(v0[k].y, v1[k].y));
            vmin[k].z = fminf(vmin[k].z, fminf(v0[k].z, v1[k].z));
            vmin[k].w = fminf(vmin[k].w, fminf(v0[k].w, v1[k].w));
        }
    }
    if (i < nact) {  // odd tail: single row
        const int r0 = s_list[wid][i];
        const float* p0 = xb + (size_t)(rowbase + r0) * ND + lane * 4;
        float4 v0[4];
        #pragma unroll
        for (int k = 0; k < 4; k++) v0[k] = *reinterpret_cast<const float4*>(p0 + k * 128);
        float d0 = dot4(v0[0], w4[0]) + dot4(v0[1], w4[1]) + dot4(v0[2], w4[2]) + dot4(v0[3], w4[3]);
        #pragma unroll
        for (int off = 16; off > 0; off >>= 1)
            d0 += __shfl_xor_sync(0xffffffffu, d0, off);
        const float newm  = fmaxf(m, d0);
        const float scale = __expf(m - newm);
        m = newm;
        l *= scale;
        const float e0 = __expf(d0 - m);
        l += e0;
        cnt += 1.f;
        #pragma unroll
        for (int k = 0; k < 4; k++) {
            vacc[k].x = vacc[k].x * scale + e0 * v0[k].x;
            vacc[k].y = vacc[k].y * scale + e0 * v0[k].y;
            vacc[k].z = vacc[k].z * scale + e0 * v0[k].z;
            vacc[k].w = vacc[k].w * scale + e0 * v0[k].w;
            vsum[k].x += v0[k].x; vsum[k].y += v0[k].y; vsum[k].z += v0[k].z; vsum[k].w += v0[k].w;
            vmax[k].x = fmaxf(vmax[k].x, v0[k].x); vmax[k].y = fmaxf(vmax[k].y, v0[k].y);
            vmax[k].z = fmaxf(vmax[k].z, v0[k].z); vmax[k].w = fmaxf(vmax[k].w, v0[k].w);
            vmin[k].x = fminf(vmin[k].x, v0[k].x); vmin[k].y = fminf(vmin[k].y, v0[k].y);
            vmin[k].z = fminf(vmin[k].z, v0[k].z); vmin[k].w = fminf(vmin[k].w, v0[k].w);
        }
    }

    // ---- once-per-CTA merge across the 4 warps
    if (lane == 0) s_m[wid] = m;
    __syncthreads();
    const float M  = fmaxf(fmaxf(s_m[0], s_m[1]), fmaxf(s_m[2], s_m[3]));
    const float sc = __expf(m - M);   // m=-1e30,M finite -> 0; both -1e30 -> 1 but l=0

    #pragma unroll
    for (int k = 0; k < 4; k++) {
        const int c = k * 128 + lane * 4;
        *reinterpret_cast<float4*>(&s_mrg[0][wid][c]) = vsum[k];
        *reinterpret_cast<float4*>(&s_mrg[1][wid][c]) = vmax[k];
        *reinterpret_cast<float4*>(&s_mrg[2][wid][c]) = vmin[k];
        float4 av = vacc[k];
        av.x *= sc; av.y *= sc; av.z *= sc; av.w *= sc;
        *reinterpret_cast<float4*>(&s_mrg[3][wid][c]) = av;
    }
    if (lane == 0) { s_l[wid] = l * sc; s_cnt[wid] = cnt; }
    __syncthreads();

    // thread t combines 4 contiguous columns across the 4 warps
    const int c0 = t * 4;
    float4 osum = *reinterpret_cast<float4*>(&s_mrg[0][0][c0]);
    float4 omax = *reinterpret_cast<float4*>(&s_mrg[1][0][c0]);
    float4 omin = *reinterpret_cast<float4*>(&s_mrg[2][0][c0]);
    float4 oacc = *reinterpret_cast<float4*>(&s_mrg[3][0][c0]);
    #pragma unroll
    for (int wi = 1; wi < 4; wi++) {
        const float4 a0 = *reinterpret_cast<float4*>(&s_mrg[0][wi][c0]);
        const float4 a1 = *reinterpret_cast<float4*>(&s_mrg[1][wi][c0]);
        const float4 a2 = *reinterpret_cast<float4*>(&s_mrg[2][wi][c0]);
        const float4 a3 = *reinterpret_cast<float4*>(&s_mrg[3][wi][c0]);
        osum.x += a0.x; osum.y += a0.y; osum.z += a0.z; osum.w += a0.w;
        omax.x = fmaxf(omax.x, a1.x); omax.y = fmaxf(omax.y, a1.y);
        omax.z = fmaxf(omax.z, a1.z); omax.w = fmaxf(omax.w, a1.w);
        omin.x = fminf(omin.x, a2.x); omin.y = fminf(omin.y, a2.y);
        omin.z = fminf(omin.z, a2.z); omin.w = fminf(omin.w, a2.w);
        oacc.x += a3.x; oacc.y += a3.y; oacc.z += a3.z; oacc.w += a3.w;
    }
    *reinterpret_cast<float4*>(&g_psum[b][chunk][c0]) = osum;
    *reinterpret_cast<float4*>(&g_pmax[b][chunk][c0]) = omax;
    *reinterpret_cast<float4*>(&g_pmin[b][chunk][c0]) = omin;
    *reinterpret_cast<float4*>(&g_pacc[b][chunk][c0]) = oacc;
    if (t == 0) {
        g_pm[b][chunk]   = M;
        g_pl[b][chunk]   = s_l[0] + s_l[1] + s_l[2] + s_l[3];
        g_pcnt[b][chunk] = s_cnt[0] + s_cnt[1] + s_cnt[2] + s_cnt[3];
    }
}

// grid (NB, 8): each block = 64 columns of one batch; 8 slices of 4 chunks over threads.
#define T2 512
#define COLS_PER_BLK 64
#define NSLICE 8
#define CHUNKS_PER_SLICE (NCHUNK / NSLICE)  // 4

__global__ __launch_bounds__(T2) void pool_pass2(float* __restrict__ out)
{
    const int b     = blockIdx.x;
    const int tid   = threadIdx.x;
    const int col   = blockIdx.y * COLS_PER_BLK + (tid & (COLS_PER_BLK - 1));
    const int slice = tid >> 6;

    __shared__ float s_sum[NSLICE][COLS_PER_BLK];
    __shared__ float s_max[NSLICE][COLS_PER_BLK];
    __shared__ float s_min[NSLICE][COLS_PER_BLK];
    __shared__ float s_acc[NSLICE][COLS_PER_BLK];

    float M = -1e30f;
    #pragma unroll
    for (int c = 0; c < NCHUNK; c++) M = fmaxf(M, g_pm[b][c]);
    float l = 0.f, cnt = 0.f;
    #pragma unroll
    for (int c = 0; c < NCHUNK; c++) {
        l   += g_pl[b][c] * __expf(g_pm[b][c] - M);
        cnt += g_pcnt[b][c];
    }

    float sum = 0.f, mx = -BIGV, mn = BIGV, acc = 0.f;
    const int cbase = slice * CHUNKS_PER_SLICE;
    #pragma unroll
    for (int ii = 0; ii < CHUNKS_PER_SLICE; ii++) {
        const int c = cbase + ii;
        sum += g_psum[b][c][col];
        mx   = fmaxf(mx, g_pmax[b][c][col]);
        mn   = fminf(mn, g_pmin[b][c][col]);
        acc += g_pacc[b][c][col] * __expf(g_pm[b][c] - M);
    }

    const int lc = tid & (COLS_PER_BLK - 1);
    s_sum[slice][lc] = sum;
    s_max[slice][lc] = mx;
    s_min[slice][lc] = mn;
    s_acc[slice][lc] = acc;
    __syncthreads();

    if (slice == 0) {
        #pragma unroll
        for (int s = 1; s < NSLICE; s++) {
            sum += s_sum[s][lc];
            mx   = fmaxf(mx, s_max[s][lc]);
            mn   = fminf(mn, s_min[s][lc]);
            acc += s_acc[s][lc];
        }
        float* ob = out + (size_t)b * (4 * ND);
        ob[col]          = sum / (cnt + 1e-6f);
        ob[ND + col]     = mx;
        ob[2 * ND + col] = mn;
        ob[3 * ND + col] = acc / l;
    }
}

extern "C" void kernel_launch(void* const* d_in, const int* in_sizes, int n_in,
                              void* d_out, int out_size)
{
    const float* x  = (const float*)d_in[0];
    const int*   mk = (const int*)d_in[1];
    const float* w  = (const float*)d_in[2];
    float* out      = (float*)d_out;

    dim3 grid1(NCHUNK, NB);
    pool_pass1<<<grid1, T1>>>(x, mk, w);
    dim3 grid2(NB, ND / COLS_PER_BLK);
    pool_pass2<<<grid2, T2>>>(out);
}

// round 5
// speedup vs baseline: 2.0381x; 1.1047x over previous
#include <cuda_runtime.h>
#include <math.h>

#define NB 32
#define NS 4096
#define ND 512
#define NCHUNK 16
#define ROWS_PER_CHUNK (NS / NCHUNK)   // 256
#define ROWS_PER_WARP  (ROWS_PER_CHUNK / 4)  // 64
#define T1 128
#define BIGV 10000.0f

__device__ float g_psum[NB][NCHUNK][ND];
__device__ float g_pmax[NB][NCHUNK][ND];
__device__ float g_pmin[NB][NCHUNK][ND];
__device__ float g_pacc[NB][NCHUNK][ND];
__device__ float g_pm [NB][NCHUNK];
__device__ float g_pl [NB][NCHUNK];
__device__ float g_pcnt[NB][NCHUNK];

__device__ __forceinline__ float dot4(const float4& a, const float4& b) {
    return a.x * b.x + a.y * b.y + a.z * b.z + a.w * b.w;
}

__global__ __launch_bounds__(T1) void pool_pass1(
    const float* __restrict__ x,
    const int* __restrict__ mask,   // 4-byte mask (int32 {0,1} or f32 {0.,1.}): nonzero-bits test exact
    const float* __restrict__ w)
{
    const int chunk = blockIdx.x;
    const int b     = blockIdx.y;
    const int t     = threadIdx.x;
    const int lane  = t & 31;
    const int wid   = t >> 5;          // warp owns 64 contiguous rows

    __shared__ int   s_list[4][ROWS_PER_WARP];
    __shared__ float s_m[4], s_l[4], s_cnt[4];
    __shared__ float s_mrg[4][4][ND];  // [type][warp][col] = 32 KB

    float4 w4[4];
    #pragma unroll
    for (int k = 0; k < 4; k++)
        w4[k] = *reinterpret_cast<const float4*>(w + k * 128 + lane * 4);

    float4 vsum[4], vmax[4], vmin[4], vacc[4];
    #pragma unroll
    for (int k = 0; k < 4; k++) {
        vsum[k] = make_float4(0.f, 0.f, 0.f, 0.f);
        vmax[k] = make_float4(-BIGV, -BIGV, -BIGV, -BIGV);
        vmin[k] = make_float4( BIGV,  BIGV,  BIGV,  BIGV);
        vacc[k] = make_float4(0.f, 0.f, 0.f, 0.f);
    }
    float m = -1e30f, l = 0.f, cnt = 0.f;

    const int rowbase = chunk * ROWS_PER_CHUNK + wid * ROWS_PER_WARP;
    const float* xb = x + (size_t)b * NS * ND;
    const int*   mb = mask + (size_t)b * NS + rowbase;

    // ---- compact 64 rows via two ballots (coalesced mask loads)
    const bool a0 = (mb[lane]      != 0);
    const bool a1 = (mb[lane + 32] != 0);
    const unsigned bal0 = __ballot_sync(0xffffffffu, a0);
    const unsigned bal1 = __ballot_sync(0xffffffffu, a1);
    const int n0 = __popc(bal0);
    if (a0) s_list[wid][__popc(bal0 & ((1u << lane) - 1u))] = lane;
    if (a1) s_list[wid][n0 + __popc(bal1 & ((1u << lane) - 1u))] = lane + 32;
    const int nact = n0 + __popc(bal1);
    __syncwarp();

    // ---- dense main loop: 4 active rows per iteration, unconditional loads
    int i = 0;
    for (; i + 4 <= nact; i += 4) {
        float4 v[4][4];
        #pragma unroll
        for (int j = 0; j < 4; j++) {
            const float* p = xb + (size_t)(rowbase + s_list[wid][i + j]) * ND + lane * 4;
            #pragma unroll
            for (int k = 0; k < 4; k++)
                v[j][k] = *reinterpret_cast<const float4*>(p + k * 128);
        }
        float d[4];
        #pragma unroll
        for (int j = 0; j < 4; j++)
            d[j] = dot4(v[j][0], w4[0]) + dot4(v[j][1], w4[1])
                 + dot4(v[j][2], w4[2]) + dot4(v[j][3], w4[3]);
        #pragma unroll
        for (int off = 16; off > 0; off >>= 1) {
            #pragma unroll
            for (int j = 0; j < 4; j++)
                d[j] += __shfl_xor_sync(0xffffffffu, d[j], off);
        }

        float newm = m;
        #pragma unroll
        for (int j = 0; j < 4; j++) newm = fmaxf(newm, d[j]);
        const float scale = __expf(m - newm);
        m = newm;
        l *= scale;
        float e[4];
        #pragma unroll
        for (int j = 0; j < 4; j++) { e[j] = __expf(d[j] - m); l += e[j]; }
        cnt += 4.f;

        #pragma unroll
        for (int k = 0; k < 4; k++) {
            float* A  = reinterpret_cast<float*>(&vacc[k]);
            float* S  = reinterpret_cast<float*>(&vsum[k]);
            float* Mx = reinterpret_cast<float*>(&vmax[k]);
            float* Mn = reinterpret_cast<float*>(&vmin[k]);
            #pragma unroll
            for (int c = 0; c < 4; c++) {
                const float x0 = reinterpret_cast<float*>(&v[0][k])[c];
                const float x1 = reinterpret_cast<float*>(&v[1][k])[c];
                const float x2 = reinterpret_cast<float*>(&v[2][k])[c];
                const float x3 = reinterpret_cast<float*>(&v[3][k])[c];
                A[c]  = A[c] * scale + e[0] * x0 + e[1] * x1 + e[2] * x2 + e[3] * x3;
                S[c] += (x0 + x1) + (x2 + x3);
                Mx[c] = fmaxf(Mx[c], fmaxf(fmaxf(x0, x1), fmaxf(x2, x3)));
                Mn[c] = fminf(Mn[c], fminf(fminf(x0, x1), fminf(x2, x3)));
            }
        }
    }
    // tail: single rows
    for (; i < nact; i++) {
        const float* p = xb + (size_t)(rowbase + s_list[wid][i]) * ND + lane * 4;
        float4 v0[4];
        #pragma unroll
        for (int k = 0; k < 4; k++) v0[k] = *reinterpret_cast<const float4*>(p + k * 128);
        float d0 = dot4(v0[0], w4[0]) + dot4(v0[1], w4[1])
                 + dot4(v0[2], w4[2]) + dot4(v0[3], w4[3]);
        #pragma unroll
        for (int off = 16; off > 0; off >>= 1)
            d0 += __shfl_xor_sync(0xffffffffu, d0, off);
        const float newm  = fmaxf(m, d0);
        const float scale = __expf(m - newm);
        m = newm;
        l *= scale;
        const float e0 = __expf(d0 - m);
        l += e0;
        cnt += 1.f;
        #pragma unroll
        for (int k = 0; k < 4; k++) {
            float* A  = reinterpret_cast<float*>(&vacc[k]);
            float* S  = reinterpret_cast<float*>(&vsum[k]);
            float* Mx = reinterpret_cast<float*>(&vmax[k]);
            float* Mn = reinterpret_cast<float*>(&vmin[k]);
            #pragma unroll
            for (int c = 0; c < 4; c++) {
                const float x0 = reinterpret_cast<float*>(&v0[k])[c];
                A[c]  = A[c] * scale + e0 * x0;
                S[c] += x0;
                Mx[c] = fmaxf(Mx[c], x0);
                Mn[c] = fminf(Mn[c], x0);
            }
        }
    }

    // ---- once-per-CTA merge across the 4 warps
    if (lane == 0) s_m[wid] = m;
    __syncthreads();
    const float M  = fmaxf(fmaxf(s_m[0], s_m[1]), fmaxf(s_m[2], s_m[3]));
    const float sc = __expf(m - M);

    #pragma unroll
    for (int k = 0; k < 4; k++) {
        const int c = k * 128 + lane * 4;
        *reinterpret_cast<float4*>(&s_mrg[0][wid][c]) = vsum[k];
        *reinterpret_cast<float4*>(&s_mrg[1][wid][c]) = vmax[k];
        *reinterpret_cast<float4*>(&s_mrg[2][wid][c]) = vmin[k];
        float4 av = vacc[k];
        av.x *= sc; av.y *= sc; av.z *= sc; av.w *= sc;
        *reinterpret_cast<float4*>(&s_mrg[3][wid][c]) = av;
    }
    if (lane == 0) { s_l[wid] = l * sc; s_cnt[wid] = cnt; }
    __syncthreads();

    const int c0 = t * 4;
    float4 osum = *reinterpret_cast<float4*>(&s_mrg[0][0][c0]);
    float4 omax = *reinterpret_cast<float4*>(&s_mrg[1][0][c0]);
    float4 omin = *reinterpret_cast<float4*>(&s_mrg[2][0][c0]);
    float4 oacc = *reinterpret_cast<float4*>(&s_mrg[3][0][c0]);
    #pragma unroll
    for (int wi = 1; wi < 4; wi++) {
        const float4 q0 = *reinterpret_cast<float4*>(&s_mrg[0][wi][c0]);
        const float4 q1 = *reinterpret_cast<float4*>(&s_mrg[1][wi][c0]);
        const float4 q2 = *reinterpret_cast<float4*>(&s_mrg[2][wi][c0]);
        const float4 q3 = *reinterpret_cast<float4*>(&s_mrg[3][wi][c0]);
        osum.x += q0.x; osum.y += q0.y; osum.z += q0.z; osum.w += q0.w;
        omax.x = fmaxf(omax.x, q1.x); omax.y = fmaxf(omax.y, q1.y);
        omax.z = fmaxf(omax.z, q1.z); omax.w = fmaxf(omax.w, q1.w);
        omin.x = fminf(omin.x, q2.x); omin.y = fminf(omin.y, q2.y);
        omin.z = fminf(omin.z, q2.z); omin.w = fminf(omin.w, q2.w);
        oacc.x += q3.x; oacc.y += q3.y; oacc.z += q3.z; oacc.w += q3.w;
    }
    *reinterpret_cast<float4*>(&g_psum[b][chunk][c0]) = osum;
    *reinterpret_cast<float4*>(&g_pmax[b][chunk][c0]) = omax;
    *reinterpret_cast<float4*>(&g_pmin[b][chunk][c0]) = omin;
    *reinterpret_cast<float4*>(&g_pacc[b][chunk][c0]) = oacc;
    if (t == 0) {
        g_pm[b][chunk]   = M;
        g_pl[b][chunk]   = s_l[0] + s_l[1] + s_l[2] + s_l[3];
        g_pcnt[b][chunk] = s_cnt[0] + s_cnt[1] + s_cnt[2] + s_cnt[3];
    }
}

// grid (NB, 8): each block = 64 columns of one batch; 8 slices of 2 chunks over threads.
#define T2 512
#define COLS_PER_BLK 64
#define NSLICE 8
#define CHUNKS_PER_SLICE (NCHUNK / NSLICE)  // 2

__global__ __launch_bounds__(T2) void pool_pass2(float* __restrict__ out)
{
    const int b     = blockIdx.x;
    const int tid   = threadIdx.x;
    const int col   = blockIdx.y * COLS_PER_BLK + (tid & (COLS_PER_BLK - 1));
    const int slice = tid >> 6;

    __shared__ float s_sum[NSLICE][COLS_PER_BLK];
    __shared__ float s_max[NSLICE][COLS_PER_BLK];
    __shared__ float s_min[NSLICE][COLS_PER_BLK];
    __shared__ float s_acc[NSLICE][COLS_PER_BLK];

    float M = -1e30f;
    #pragma unroll
    for (int c = 0; c < NCHUNK; c++) M = fmaxf(M, g_pm[b][c]);
    float l = 0.f, cnt = 0.f;
    #pragma unroll
    for (int c = 0; c < NCHUNK; c++) {
        l   += g_pl[b][c] * __expf(g_pm[b][c] - M);
        cnt += g_pcnt[b][c];
    }

    float sum = 0.f, mx = -BIGV, mn = BIGV, acc = 0.f;
    const int cbase = slice * CHUNKS_PER_SLICE;
    #pragma unroll
    for (int ii = 0; ii < CHUNKS_PER_SLICE; ii++) {
        const int c = cbase + ii;
        sum += g_psum[b][c][col];
        mx   = fmaxf(mx, g_pmax[b][c][col]);
        mn   = fminf(mn, g_pmin[b][c][col]);
        acc += g_pacc[b][c][col] * __expf(g_pm[b][c] - M);
    }

    const int lc = tid & (COLS_PER_BLK - 1);
    s_sum[slice][lc] = sum;
    s_max[slice][lc] = mx;
    s_min[slice][lc] = mn;
    s_acc[slice][lc] = acc;
    __syncthreads();

    if (slice == 0) {
        #pragma unroll
        for (int s = 1; s < NSLICE; s++) {
            sum += s_sum[s][lc];
            mx   = fmaxf(mx, s_max[s][lc]);
            mn   = fminf(mn, s_min[s][lc]);
            acc += s_acc[s][lc];
        }
        float* ob = out + (size_t)b * (4 * ND);
        ob[col]          = sum / (cnt + 1e-6f);
        ob[ND + col]     = mx;
        ob[2 * ND + col] = mn;
        ob[3 * ND + col] = acc / l;
    }
}

extern "C" void kernel_launch(void* const* d_in, const int* in_sizes, int n_in,
                              void* d_out, int out_size)
{
    const float* x  = (const float*)d_in[0];
    const int*   mk = (const int*)d_in[1];
    const float* w  = (const float*)d_in[2];
    float* out      = (float*)d_out;

    dim3 grid1(NCHUNK, NB);   // (16, 32) = 512 CTAs
    pool_pass1<<<grid1, T1>>>(x, mk, w);
    dim3 grid2(NB, ND / COLS_PER_BLK);  // (32, 8)
    pool_pass2<<<grid2, T2>>>(out);
}

// round 7
// speedup vs baseline: 2.1517x; 1.0557x over previous
#include <cuda_runtime.h>
#include <math.h>

#define NB 32
#define NS 4096
#define ND 512
#define NCHUNK 32
#define ROWS_PER_CHUNK (NS / NCHUNK)        // 128
#define ROWS_PER_WARP  (ROWS_PER_CHUNK / 4) // 32
#define T1 128
#define BIGV 10000.0f

__device__ float g_psum[NB][NCHUNK][ND];
__device__ float g_pmax[NB][NCHUNK][ND];
__device__ float g_pmin[NB][NCHUNK][ND];
__device__ float g_pacc[NB][NCHUNK][ND];
__device__ float g_pm [NB][NCHUNK];
__device__ float g_pl [NB][NCHUNK];
__device__ float g_pcnt[NB][NCHUNK];

__device__ __forceinline__ float dot4(const float4& a, const float4& b) {
    return a.x * b.x + a.y * b.y + a.z * b.z + a.w * b.w;
}

__global__ __launch_bounds__(T1) void pool_pass1(
    const float* __restrict__ x,
    const int* __restrict__ mask,   // 4-byte mask (int32 {0,1} or f32 {0.,1.}): nonzero-bits test exact
    const float* __restrict__ w)
{
    const int chunk = blockIdx.x;
    const int b     = blockIdx.y;
    const int t     = threadIdx.x;
    const int lane  = t & 31;
    const int wid   = t >> 5;            // warp owns 32 contiguous rows

    __shared__ int   s_list[4][ROWS_PER_WARP];
    __shared__ float s_m[4], s_l[4], s_cnt[4];
    __shared__ float s_mrg[2][4][ND];    // two planes, reused in two merge stages (16 KB)

    float4 w4[4];
    #pragma unroll
    for (int k = 0; k < 4; k++)
        w4[k] = *reinterpret_cast<const float4*>(w + k * 128 + lane * 4);

    float4 vsum[4], vmax[4], vmin[4], vacc[4];
    #pragma unroll
    for (int k = 0; k < 4; k++) {
        vsum[k] = make_float4(0.f, 0.f, 0.f, 0.f);
        vmax[k] = make_float4(-BIGV, -BIGV, -BIGV, -BIGV);
        vmin[k] = make_float4( BIGV,  BIGV,  BIGV,  BIGV);
        vacc[k] = make_float4(0.f, 0.f, 0.f, 0.f);
    }
    float m = -1e30f, l = 0.f, cnt = 0.f;

    const int rowbase = chunk * ROWS_PER_CHUNK + wid * ROWS_PER_WARP;
    const float* xb = x + (size_t)b * NS * ND;

    // ---- compact 32 rows via ballot (coalesced mask load)
    const bool a = (mask[(size_t)b * NS + rowbase + lane] != 0);
    const unsigned bal = __ballot_sync(0xffffffffu, a);
    if (a) s_list[wid][__popc(bal & ((1u << lane) - 1u))] = lane;
    const int nact = __popc(bal);
    __syncwarp();

    // ---- dense main loop: 4 active rows per iteration, unconditional loads
    int i = 0;
    for (; i + 4 <= nact; i += 4) {
        float4 v[4][4];
        #pragma unroll
        for (int j = 0; j < 4; j++) {
            const float* p = xb + (size_t)(rowbase + s_list[wid][i + j]) * ND + lane * 4;
            #pragma unroll
            for (int k = 0; k < 4; k++)
                v[j][k] = *reinterpret_cast<const float4*>(p + k * 128);
        }
        float d[4];
        #pragma unroll
        for (int j = 0; j < 4; j++)
            d[j] = dot4(v[j][0], w4[0]) + dot4(v[j][1], w4[1])
                 + dot4(v[j][2], w4[2]) + dot4(v[j][3], w4[3]);
        #pragma unroll
        for (int off = 16; off > 0; off >>= 1) {
            #pragma unroll
            for (int j = 0; j < 4; j++)
                d[j] += __shfl_xor_sync(0xffffffffu, d[j], off);
        }

        float newm = m;
        #pragma unroll
        for (int j = 0; j < 4; j++) newm = fmaxf(newm, d[j]);
        const float scale = __expf(m - newm);
        m = newm;
        l *= scale;
        float e[4];
        #pragma unroll
        for (int j = 0; j < 4; j++) { e[j] = __expf(d[j] - m); l += e[j]; }
        cnt += 4.f;

        #pragma unroll
        for (int k = 0; k < 4; k++) {
            float* A  = reinterpret_cast<float*>(&vacc[k]);
            float* S  = reinterpret_cast<float*>(&vsum[k]);
            float* Mx = reinterpret_cast<float*>(&vmax[k]);
            float* Mn = reinterpret_cast<float*>(&vmin[k]);
            #pragma unroll
            for (int c = 0; c < 4; c++) {
                const float x0 = reinterpret_cast<float*>(&v[0][k])[c];
                const float x1 = reinterpret_cast<float*>(&v[1][k])[c];
                const float x2 = reinterpret_cast<float*>(&v[2][k])[c];
                const float x3 = reinterpret_cast<float*>(&v[3][k])[c];
                A[c]  = A[c] * scale + e[0] * x0 + e[1] * x1 + e[2] * x2 + e[3] * x3;
                S[c] += (x0 + x1) + (x2 + x3);
                Mx[c] = fmaxf(Mx[c], fmaxf(fmaxf(x0, x1), fmaxf(x2, x3)));
                Mn[c] = fminf(Mn[c], fminf(fminf(x0, x1), fminf(x2, x3)));
            }
        }
    }
    for (; i < nact; i++) {   // tail
        const float* p = xb + (size_t)(rowbase + s_list[wid][i]) * ND + lane * 4;
        float4 v0[4];
        #pragma unroll
        for (int k = 0; k < 4; k++) v0[k] = *reinterpret_cast<const float4*>(p + k * 128);
        float d0 = dot4(v0[0], w4[0]) + dot4(v0[1], w4[1])
                 + dot4(v0[2], w4[2]) + dot4(v0[3], w4[3]);
        #pragma unroll
        for (int off = 16; off > 0; off >>= 1)
            d0 += __shfl_xor_sync(0xffffffffu, d0, off);
        const float newm  = fmaxf(m, d0);
        const float scale = __expf(m - newm);
        m = newm;
        l *= scale;
        const float e0 = __expf(d0 - m);
        l += e0;
        cnt += 1.f;
        #pragma unroll
        for (int k = 0; k < 4; k++) {
            float* A  = reinterpret_cast<float*>(&vacc[k]);
            float* S  = reinterpret_cast<float*>(&vsum[k]);
            float* Mx = reinterpret_cast<float*>(&vmax[k]);
            float* Mn = reinterpret_cast<float*>(&vmin[k]);
            #pragma unroll
            for (int c = 0; c < 4; c++) {
                const float x0 = reinterpret_cast<float*>(&v0[k])[c];
                A[c]  = A[c] * scale + e0 * x0;
                S[c] += x0;
                Mx[c] = fmaxf(Mx[c], x0);
                Mn[c] = fminf(Mn[c], x0);
            }
        }
    }

    // ---- two-stage merge across 4 warps (smem plane reuse)
    if (lane == 0) { s_m[wid] = m; s_cnt[wid] = cnt; }
    // stage A: sum + max
    #pragma unroll
    for (int k = 0; k < 4; k++) {
        const int c = k * 128 + lane * 4;
        *reinterpret_cast<float4*>(&s_mrg[0][wid][c]) = vsum[k];
        *reinterpret_cast<float4*>(&s_mrg[1][wid][c]) = vmax[k];
    }
    __syncthreads();

    const float M  = fmaxf(fmaxf(s_m[0], s_m[1]), fmaxf(s_m[2], s_m[3]));
    const float sc = __expf(m - M);

    const int c0 = t * 4;
    {
        float4 osum = *reinterpret_cast<float4*>(&s_mrg[0][0][c0]);
        float4 omax = *reinterpret_cast<float4*>(&s_mrg[1][0][c0]);
        #pragma unroll
        for (int wi = 1; wi < 4; wi++) {
            const float4 q0 = *reinterpret_cast<float4*>(&s_mrg[0][wi][c0]);
            const float4 q1 = *reinterpret_cast<float4*>(&s_mrg[1][wi][c0]);
            osum.x += q0.x; osum.y += q0.y; osum.z += q0.z; osum.w += q0.w;
            omax.x = fmaxf(omax.x, q1.x); omax.y = fmaxf(omax.y, q1.y);
            omax.z = fmaxf(omax.z, q1.z); omax.w = fmaxf(omax.w, q1.w);
        }
        *reinterpret_cast<float4*>(&g_psum[b][chunk][c0]) = osum;
        *reinterpret_cast<float4*>(&g_pmax[b][chunk][c0]) = omax;
    }
    __syncthreads();   // protect plane reuse

    // stage B: min + acc (scaled to block max)
    #pragma unroll
    for (int k = 0; k < 4; k++) {
        const int c = k * 128 + lane * 4;
        *reinterpret_cast<float4*>(&s_mrg[0][wid][c]) = vmin[k];
        float4 av = vacc[k];
        av.x *= sc; av.y *= sc; av.z *= sc; av.w *= sc;
        *reinterpret_cast<float4*>(&s_mrg[1][wid][c]) = av;
    }
    if (lane == 0) s_l[wid] = l * sc;
    __syncthreads();

    {
        float4 omin = *reinterpret_cast<float4*>(&s_mrg[0][0][c0]);
        float4 oacc = *reinterpret_cast<float4*>(&s_mrg[1][0][c0]);
        #pragma unroll
        for (int wi = 1; wi < 4; wi++) {
            const float4 q0 = *reinterpret_cast<float4*>(&s_mrg[0][wi][c0]);
            const float4 q1 = *reinterpret_cast<float4*>(&s_mrg[1][wi][c0]);
            omin.x = fminf(omin.x, q0.x); omin.y = fminf(omin.y, q0.y);
            omin.z = fminf(omin.z, q0.z); omin.w = fminf(omin.w, q0.w);
            oacc.x += q1.x; oacc.y += q1.y; oacc.z += q1.z; oacc.w += q1.w;
        }
        *reinterpret_cast<float4*>(&g_pmin[b][chunk][c0]) = omin;
        *reinterpret_cast<float4*>(&g_pacc[b][chunk][c0]) = oacc;
    }
    if (t == 0) {
        g_pm[b][chunk]   = M;
        g_pl[b][chunk]   = s_l[0] + s_l[1] + s_l[2] + s_l[3];
        g_pcnt[b][chunk] = s_cnt[0] + s_cnt[1] + s_cnt[2] + s_cnt[3];
    }
}

// pass2: grid (NB, 8); block = 64 columns × 8 chunk-slices; warp 0 precomputes
// per-batch normalized softmax weights once (kills the per-thread scalar prologue).
#define T2 512
#define COLS_PER_BLK 64
#define NSLICE 8
#define CHUNKS_PER_SLICE (NCHUNK / NSLICE)  // 4

__global__ __launch_bounds__(T2) void pool_pass2(float* __restrict__ out)
{
    const int b     = blockIdx.x;
    const int tid   = threadIdx.x;
    const int col   = blockIdx.y * COLS_PER_BLK + (tid & (COLS_PER_BLK - 1));
    const int slice = tid >> 6;

    __shared__ float s_wc[NCHUNK];   // exp(m_c - M) / L
    __shared__ float s_invcnt;
    __shared__ float s_sum[NSLICE][COLS_PER_BLK];
    __shared__ float s_max[NSLICE][COLS_PER_BLK];
    __shared__ float s_min[NSLICE][COLS_PER_BLK];
    __shared__ float s_acc[NSLICE][COLS_PER_BLK];

    if (tid < 32) {   // one lane per chunk
        const float mc = g_pm[b][tid];
        const float lc = g_pl[b][tid];
        const float cc = g_pcnt[b][tid];
        float M = mc;
        #pragma unroll
        for (int off = 16; off > 0; off >>= 1)
            M = fmaxf(M, __shfl_xor_sync(0xffffffffu, M, off));
        const float ec = __expf(mc - M);
        float L = lc * ec, C = cc;
        #pragma unroll
        for (int off = 16; off > 0; off >>= 1) {
            L += __shfl_xor_sync(0xffffffffu, L, off);
            C += __shfl_xor_sync(0xffffffffu, C, off);
        }
        s_wc[tid] = ec / L;
        if (tid == 0) s_invcnt = 1.f / (C + 1e-6f);
    }
    __syncthreads();

    float sum = 0.f, mx = -BIGV, mn = BIGV, acc = 0.f;
    const int cbase = slice * CHUNKS_PER_SLICE;
    #pragma unroll
    for (int ii = 0; ii < CHUNKS_PER_SLICE; ii++) {
        const int c = cbase + ii;
        sum += g_psum[b][c][col];
        mx   = fmaxf(mx, g_pmax[b][c][col]);
        mn   = fminf(mn, g_pmin[b][c][col]);
        acc += g_pacc[b][c][col] * s_wc[c];
    }

    const int lc2 = tid & (COLS_PER_BLK - 1);
    s_sum[slice][lc2] = sum;
    s_max[slice][lc2] = mx;
    s_min[slice][lc2] = mn;
    s_acc[slice][lc2] = acc;
    __syncthreads();

    if (slice == 0) {
        #pragma unroll
        for (int s = 1; s < NSLICE; s++) {
            sum += s_sum[s][lc2];
            mx   = fmaxf(mx, s_max[s][lc2]);
            mn   = fminf(mn, s_min[s][lc2]);
            acc += s_acc[s][lc2];
        }
        float* ob = out + (size_t)b * (4 * ND);
        ob[col]          = sum * s_invcnt;
        ob[ND + col]     = mx;
        ob[2 * ND + col] = mn;
        ob[3 * ND + col] = acc;     // weights already normalized by 1/L
    }
}

extern "C" void kernel_launch(void* const* d_in, const int* in_sizes, int n_in,
                              void* d_out, int out_size)
{
    const float* x  = (const float*)d_in[0];
    const int*   mk = (const int*)d_in[1];
    const float* w  = (const float*)d_in[2];
    float* out      = (float*)d_out;

    dim3 grid1(NCHUNK, NB);   // (32, 32) = 1024 CTAs
    pool_pass1<<<grid1, T1>>>(x, mk, w);
    dim3 grid2(NB, ND / COLS_PER_BLK);   // (32, 8)
    pool_pass2<<<grid2, T2>>>(out);
}